// round 9
// baseline (speedup 1.0000x reference)
#include <cuda_runtime.h>
#include <cuda_bf16.h>
#include <math.h>
#include <stdint.h>

#define BB 512
#define TT 512
#define DD 128
#define HH 64

// Scratch, row-major: g_pre[row=b*TT+t][64], g_ball[row][8]. +8 pad rows for
// the scan's prefetch (pad values loaded but never consumed).
__device__ float g_pre[((size_t)BB * TT + 8) * HH];
__device__ float g_ball[((size_t)BB * TT + 8) * 8];

// ---------------- helpers ----------------
__device__ __forceinline__ uint32_t s2u(const void* p) {
    uint32_t a;
    asm("{ .reg .u64 t; cvta.to.shared.u64 t, %1; cvt.u32.u64 %0, t; }"
        : "=r"(a) : "l"(p));
    return a;
}
__device__ __forceinline__ void ldsm4(uint32_t addr, uint32_t& r0, uint32_t& r1,
                                      uint32_t& r2, uint32_t& r3) {
    asm volatile("ldmatrix.sync.aligned.m8n8.x4.shared.b16 {%0,%1,%2,%3}, [%4];"
                 : "=r"(r0), "=r"(r1), "=r"(r2), "=r"(r3) : "r"(addr));
}
__device__ __forceinline__ void ldsm4t(uint32_t addr, uint32_t& r0, uint32_t& r1,
                                       uint32_t& r2, uint32_t& r3) {
    asm volatile("ldmatrix.sync.aligned.m8n8.x4.trans.shared.b16 {%0,%1,%2,%3}, [%4];"
                 : "=r"(r0), "=r"(r1), "=r"(r2), "=r"(r3) : "r"(addr));
}
__device__ __forceinline__ void ldsm2t(uint32_t addr, uint32_t& r0, uint32_t& r1) {
    asm volatile("ldmatrix.sync.aligned.m8n8.x2.trans.shared.b16 {%0,%1}, [%2];"
                 : "=r"(r0), "=r"(r1) : "r"(addr));
}
__device__ __forceinline__ void mma16816(float* c, uint32_t a0, uint32_t a1,
                                         uint32_t a2, uint32_t a3, uint32_t b0,
                                         uint32_t b1) {
    asm volatile(
        "mma.sync.aligned.m16n8k16.row.col.f32.bf16.bf16.f32 "
        "{%0,%1,%2,%3},{%4,%5,%6,%7},{%8,%9},{%0,%1,%2,%3};"
        : "+f"(c[0]), "+f"(c[1]), "+f"(c[2]), "+f"(c[3])
        : "r"(a0), "r"(a1), "r"(a2), "r"(a3), "r"(b0), "r"(b1));
}
__device__ __forceinline__ void split2(float a, float b, uint32_t& hi, uint32_t& lo) {
    uint32_t h;
    asm("cvt.rn.bf16x2.f32 %0, %1, %2;" : "=r"(h) : "f"(b), "f"(a));
    float ah = __uint_as_float(h << 16);
    float bh = __uint_as_float(h & 0xFFFF0000u);
    float al = a - ah, bl = b - bh;
    uint32_t l;
    asm("cvt.rn.bf16x2.f32 %0, %1, %2;" : "=r"(l) : "f"(bl), "f"(al));
    hi = h;
    lo = l;
}
__device__ __forceinline__ float tanh_fast(float x) {
    float y;
    asm("tanh.approx.f32 %0, %1;" : "=f"(y) : "f"(x));
    return y;
}
__device__ __forceinline__ float gelu_fast(float x) {
    float x2 = x * x;
    float u = x * fmaf(x2, 0.0356774081f, 0.7978845608f);
    float t = tanh_fast(u);
    return x * fmaf(t, 0.5f, 0.5f);
}
__device__ __forceinline__ int redux_add_s32(int v) {
    int r;
    asm("redux.sync.add.s32 %0, %1, 0xffffffff;" : "=r"(r) : "r"(v));
    return r;
}
__device__ __forceinline__ float sigmoidf_(float v) { return 1.0f / (1.0f + expf(-v)); }

// =====================================================================
// Phase 1 (TC v2): block = 128 token rows, 256 threads (8 warps).
// Full W1 staged once; x double-buffered per 32-K chunk; bf16-split HMMA.
// =====================================================================
// smem layout (bytes):
//  phase A: aHi@0(10240) aLo@10240(10240) w1Hi@20480(18432) w1Lo@38912(18432)
//  phase B overlay: hHi@0(18432) hLo@18432(18432)
//  w2Hi@57344(11264) w2Lo@68608(11264) sLng@79872(256) sLnb@80128(256)
#define P1_SMEM_BYTES 80384
#define SA 40  // A plane row stride (elements)
#define SW 72  // W1/h plane stride
#define S2 88  // W2 plane stride

__global__ __launch_bounds__(256, 2) void phase1_kernel(
    const float* __restrict__ x, const float* __restrict__ W1,
    const float* __restrict__ b1, const float* __restrict__ ln_g,
    const float* __restrict__ ln_b, const float* __restrict__ W_inn,
    const float* __restrict__ b_inn, const float* __restrict__ Wc1,
    const float* __restrict__ bc1) {
    extern __shared__ char sm[];
    __nv_bfloat16* aHi = (__nv_bfloat16*)(sm + 0);
    __nv_bfloat16* aLo = (__nv_bfloat16*)(sm + 10240);
    __nv_bfloat16* w1Hi = (__nv_bfloat16*)(sm + 20480);
    __nv_bfloat16* w1Lo = (__nv_bfloat16*)(sm + 38912);
    __nv_bfloat16* hHi = (__nv_bfloat16*)(sm + 0);
    __nv_bfloat16* hLo = (__nv_bfloat16*)(sm + 18432);
    __nv_bfloat16* w2Hi = (__nv_bfloat16*)(sm + 57344);
    __nv_bfloat16* w2Lo = (__nv_bfloat16*)(sm + 68608);
    float* sLng = (float*)(sm + 79872);
    float* sLnb = (float*)(sm + 80128);

    const int tid = threadIdx.x;
    const int lane = tid & 31, warp = tid >> 5;
    const int lm16 = lane & 15, lh16 = lane >> 4;
    const int qr = lane >> 2, qc = (lane & 3) * 2;
    const int row0 = blockIdx.x * 128;

    // prologue: prefetch x chunk0 into registers
    float4 xr[4];
#pragma unroll
    for (int j = 0; j < 4; j++) {
        int i = tid + j * 256, r = i >> 3, kq = i & 7;
        xr[j] = __ldg(reinterpret_cast<const float4*>(x + (size_t)(row0 + r) * DD) + kq);
    }

    // stage FULL W1 (hi/lo split) once
    for (int i = tid; i < DD * HH; i += 256) {
        int k = i >> 6, n = i & 63;
        float f = W1[i];
        __nv_bfloat16 h = __float2bfloat16(f);
        __nv_bfloat16 l = __float2bfloat16(f - __bfloat162float(h));
        w1Hi[k * SW + n] = h;
        w1Lo[k * SW + n] = l;
    }

    // W2comb = [Wc1_h (64x64) | W_inn (64x5) | 0-pad (64x3)] (no idiv)
    {
        int k = tid >> 2;
        int nb = (tid & 3) * 18;
#pragma unroll 1
        for (int nn = 0; nn < 18; nn++) {
            int n = nb + nn;
            float f = (n < 64) ? Wc1[(5 + k) * 64 + n]
                               : (n < 69 ? W_inn[k * 5 + (n - 64)] : 0.0f);
            __nv_bfloat16 h = __float2bfloat16(f);
            __nv_bfloat16 l = __float2bfloat16(f - __bfloat162float(h));
            w2Hi[k * S2 + n] = h;
            w2Lo[k * S2 + n] = l;
        }
    }
    if (tid < 64) {
        sLng[tid] = ln_g[tid];
        sLnb[tid] = ln_b[tid];
    }

    // ---- GEMM1 accumulators, init = b1[col] (added pre-LN) ----
    float acc[8][4];
#pragma unroll
    for (int t8 = 0; t8 < 8; t8++) {
        int col = t8 * 8 + qc;
        acc[t8][0] = __ldg(b1 + col);
        acc[t8][1] = __ldg(b1 + col + 1);
        acc[t8][2] = acc[t8][0];
        acc[t8][3] = acc[t8][1];
    }

    const uint32_t uaH = s2u(aHi) + 2 * ((warp * 16 + lm16) * SA + 8 * lh16);
    const uint32_t uaL = s2u(aLo) + 2 * ((warp * 16 + lm16) * SA + 8 * lh16);
    const uint32_t uwH = s2u(w1Hi) + 2 * (lm16 * SW + 8 * lh16);
    const uint32_t uwL = s2u(w1Lo) + 2 * (lm16 * SW + 8 * lh16);

#pragma unroll 1
    for (int c = 0; c < 4; c++) {
        __syncthreads();  // previous chunk's A-plane reads done (covers W1 stage on c=0)
#pragma unroll
        for (int j = 0; j < 4; j++) {
            int i = tid + j * 256, r = i >> 3, kq = i & 7;
            uint32_t h0, l0, h1, l1;
            split2(xr[j].x, xr[j].y, h0, l0);
            split2(xr[j].z, xr[j].w, h1, l1);
            int e = r * SA + kq * 4;
            *(uint32_t*)&aHi[e] = h0;
            *(uint32_t*)&aHi[e + 2] = h1;
            *(uint32_t*)&aLo[e] = l0;
            *(uint32_t*)&aLo[e + 2] = l1;
        }
        __syncthreads();
        if (c < 3) {
#pragma unroll
            for (int j = 0; j < 4; j++) {
                int i = tid + j * 256, r = i >> 3, kq = i & 7;
                xr[j] = __ldg(reinterpret_cast<const float4*>(
                                  x + (size_t)(row0 + r) * DD + (c + 1) * 32) + kq);
            }
        }
#pragma unroll
        for (int ks = 0; ks < 2; ks++) {
            uint32_t ah0, ah1, ah2, ah3, al0, al1, al2, al3;
            ldsm4(uaH + ks * 32, ah0, ah1, ah2, ah3);
            ldsm4(uaL + ks * 32, al0, al1, al2, al3);
#pragma unroll
            for (int p = 0; p < 4; p++) {
                uint32_t off = (uint32_t)(c * 32 + ks * 16) * SW * 2 + p * 32;
                uint32_t bh0, bh1, bh2, bh3, bl0, bl1, bl2, bl3;
                ldsm4t(uwH + off, bh0, bh1, bh2, bh3);
                ldsm4t(uwL + off, bl0, bl1, bl2, bl3);
                mma16816(acc[2 * p], ah0, ah1, ah2, ah3, bh0, bh1);
                mma16816(acc[2 * p], ah0, ah1, ah2, ah3, bl0, bl1);
                mma16816(acc[2 * p], al0, al1, al2, al3, bh0, bh1);
                mma16816(acc[2 * p + 1], ah0, ah1, ah2, ah3, bh2, bh3);
                mma16816(acc[2 * p + 1], ah0, ah1, ah2, ah3, bl2, bl3);
                mma16816(acc[2 * p + 1], al0, al1, al2, al3, bh2, bh3);
            }
        }
    }

    // ---- LN (stats via quad shuffles) + gelu + split into h planes ----
    float sA = 0.f, qA = 0.f, sB = 0.f, qB = 0.f;
#pragma unroll
    for (int t8 = 0; t8 < 8; t8++) {
        sA += acc[t8][0] + acc[t8][1];
        qA += acc[t8][0] * acc[t8][0] + acc[t8][1] * acc[t8][1];
        sB += acc[t8][2] + acc[t8][3];
        qB += acc[t8][2] * acc[t8][2] + acc[t8][3] * acc[t8][3];
    }
#pragma unroll
    for (int m = 1; m <= 2; m <<= 1) {
        sA += __shfl_xor_sync(0xffffffffu, sA, m);
        qA += __shfl_xor_sync(0xffffffffu, qA, m);
        sB += __shfl_xor_sync(0xffffffffu, sB, m);
        qB += __shfl_xor_sync(0xffffffffu, qB, m);
    }
    float mA = sA * (1.0f / 64), vA = qA * (1.0f / 64) - mA * mA;
    float rA_ = rsqrtf(vA + 1e-5f);
    float mB = sB * (1.0f / 64), vB = qB * (1.0f / 64) - mB * mB;
    float rB_ = rsqrtf(vB + 1e-5f);

    __syncthreads();  // all warps done reading A/W1 planes (overlay with h)

    const int rA = warp * 16 + qr, rB = rA + 8;
#pragma unroll
    for (int t8 = 0; t8 < 8; t8++) {
        int col = t8 * 8 + qc;
        float g0 = sLng[col], g1 = sLng[col + 1];
        float bb0 = sLnb[col], bb1 = sLnb[col + 1];
        float vA0 = gelu_fast(fmaf((acc[t8][0] - mA) * rA_, g0, bb0));
        float vA1 = gelu_fast(fmaf((acc[t8][1] - mA) * rA_, g1, bb1));
        float vB0 = gelu_fast(fmaf((acc[t8][2] - mB) * rB_, g0, bb0));
        float vB1 = gelu_fast(fmaf((acc[t8][3] - mB) * rB_, g1, bb1));
        uint32_t h01, l01;
        split2(vA0, vA1, h01, l01);
        *(uint32_t*)&hHi[rA * SW + col] = h01;
        *(uint32_t*)&hLo[rA * SW + col] = l01;
        split2(vB0, vB1, h01, l01);
        *(uint32_t*)&hHi[rB * SW + col] = h01;
        *(uint32_t*)&hLo[rB * SW + col] = l01;
    }
    __syncthreads();

    // ---- GEMM2: [pre | ball] = h @ W2comb + [bc1 | b_inn | 0] ----
    float ac2[9][4];
#pragma unroll
    for (int t8 = 0; t8 < 8; t8++) {
        int col = t8 * 8 + qc;
        ac2[t8][0] = __ldg(bc1 + col);
        ac2[t8][1] = __ldg(bc1 + col + 1);
        ac2[t8][2] = ac2[t8][0];
        ac2[t8][3] = ac2[t8][1];
    }
    ac2[8][0] = (qc < 5) ? __ldg(b_inn + qc) : 0.0f;
    ac2[8][1] = (qc + 1 < 5) ? __ldg(b_inn + qc + 1) : 0.0f;
    ac2[8][2] = ac2[8][0];
    ac2[8][3] = ac2[8][1];

    const uint32_t uhH = s2u(hHi) + 2 * ((warp * 16 + lm16) * SW + 8 * lh16);
    const uint32_t uhL = s2u(hLo) + 2 * ((warp * 16 + lm16) * SW + 8 * lh16);
    const uint32_t u2H = s2u(w2Hi) + 2 * (lm16 * S2 + 8 * lh16);
    const uint32_t u2L = s2u(w2Lo) + 2 * (lm16 * S2 + 8 * lh16);
    const uint32_t u8H = s2u(w2Hi) + 2 * (lm16 * S2 + 64);
    const uint32_t u8L = s2u(w2Lo) + 2 * (lm16 * S2 + 64);

#pragma unroll
    for (int ks = 0; ks < 4; ks++) {
        uint32_t ah0, ah1, ah2, ah3, al0, al1, al2, al3;
        ldsm4(uhH + ks * 32, ah0, ah1, ah2, ah3);
        ldsm4(uhL + ks * 32, al0, al1, al2, al3);
#pragma unroll
        for (int p = 0; p < 4; p++) {
            uint32_t off = ks * (16 * S2 * 2) + p * 32;
            uint32_t bh0, bh1, bh2, bh3, bl0, bl1, bl2, bl3;
            ldsm4t(u2H + off, bh0, bh1, bh2, bh3);
            ldsm4t(u2L + off, bl0, bl1, bl2, bl3);
            mma16816(ac2[2 * p], ah0, ah1, ah2, ah3, bh0, bh1);
            mma16816(ac2[2 * p], ah0, ah1, ah2, ah3, bl0, bl1);
            mma16816(ac2[2 * p], al0, al1, al2, al3, bh0, bh1);
            mma16816(ac2[2 * p + 1], ah0, ah1, ah2, ah3, bh2, bh3);
            mma16816(ac2[2 * p + 1], ah0, ah1, ah2, ah3, bl2, bl3);
            mma16816(ac2[2 * p + 1], al0, al1, al2, al3, bh2, bh3);
        }
        uint32_t b80, b81, c80, c81;
        ldsm2t(u8H + ks * (16 * S2 * 2), b80, b81);
        ldsm2t(u8L + ks * (16 * S2 * 2), c80, c81);
        mma16816(ac2[8], ah0, ah1, ah2, ah3, b80, b81);
        mma16816(ac2[8], ah0, ah1, ah2, ah3, c80, c81);
        mma16816(ac2[8], al0, al1, al2, al3, b80, b81);
    }

    // ---- store pre (rows contiguous 256B) + ball ----
    const int growA = row0 + warp * 16 + qr;
#pragma unroll
    for (int t8 = 0; t8 < 8; t8++) {
        int col = t8 * 8 + qc;
        *(float2*)&g_pre[(size_t)growA * 64 + col] = make_float2(ac2[t8][0], ac2[t8][1]);
        *(float2*)&g_pre[(size_t)(growA + 8) * 64 + col] =
            make_float2(ac2[t8][2], ac2[t8][3]);
    }
    *(float2*)&g_ball[(size_t)growA * 8 + qc] = make_float2(ac2[8][0], ac2[8][1]);
    *(float2*)&g_ball[(size_t)(growA + 8) * 8 + qc] = make_float2(ac2[8][2], ac2[8][3]);
}

// =====================================================================
// Phase 2 scan (v6): TWO independent batch rows per warp, software-
// pipelined (chains overlap). 256 single-warp CTAs. Fixed-point REDUX.
// Depth-4 register prefetch per row.
// =====================================================================
#define FXS 1048576.0f
#define FXSI 9.5367431640625e-7f

__global__ __launch_bounds__(32) void scan_kernel(
    const float* __restrict__ Wc1, const float* __restrict__ Wc2,
    const float* __restrict__ bc2, const float* __restrict__ corr_scale,
    const float* __restrict__ raw_aL, const float* __restrict__ raw_aT,
    const float* __restrict__ raw_g, const float* __restrict__ raw_aR,
    const float* __restrict__ omega, float* __restrict__ out) {
    const int lane = threadIdx.x;
    const int rowA = blockIdx.x * 2;
    const int rowB = rowA + 1;
    const int j0 = lane * 2;

    float w1s[5][2], w2v[2][5], bc[5];
#pragma unroll
    for (int k = 0; k < 5; k++) {
        w1s[k][0] = __ldg(&Wc1[k * 64 + j0]);
        w1s[k][1] = __ldg(&Wc1[k * 64 + j0 + 1]);
    }
#pragma unroll
    for (int jj = 0; jj < 2; jj++)
#pragma unroll
        for (int k = 0; k < 5; k++) w2v[jj][k] = __ldg(&Wc2[(j0 + jj) * 5 + k]) * FXS;
#pragma unroll
    for (int k = 0; k < 5; k++) bc[k] = __ldg(bc2 + k);

    const float aL = sigmoidf_(__ldg(raw_aL)) * 0.15f + 0.85f;
    const float aT = sigmoidf_(__ldg(raw_aT)) * 0.25f + 0.70f;
    const float gg = sigmoidf_(__ldg(raw_g)) * 0.20f + 0.80f;
    const float aR = sigmoidf_(__ldg(raw_aR)) * 0.40f;
    const float om = __ldg(omega);
    const float gc = gg * cosf(om), gs = gg * sinf(om), ngs = -gs;
    const float cs = __ldg(corr_scale);

    float sA0 = 0.f, sA1 = 0.f, sA2 = 0.f, sA3 = 0.f, sA4 = 0.f;
    float sB0 = 0.f, sB1 = 0.f, sB2 = 0.f, sB3 = 0.f, sB4 = 0.f;

    float2 pA[4], pB[4];
    float bA[4][5], bB[4][5];
#pragma unroll
    for (int u = 0; u < 4; u++) {
        pA[u] = __ldg(reinterpret_cast<const float2*>(
            g_pre + ((size_t)rowA * TT + u) * HH + j0));
        pB[u] = __ldg(reinterpret_cast<const float2*>(
            g_pre + ((size_t)rowB * TT + u) * HH + j0));
        const float* ap = g_ball + ((size_t)rowA * TT + u) * 8;
        float4 c4 = __ldg(reinterpret_cast<const float4*>(ap));
        bA[u][0] = c4.x; bA[u][1] = c4.y; bA[u][2] = c4.z; bA[u][3] = c4.w;
        bA[u][4] = __ldg(ap + 4);
        const float* bp = g_ball + ((size_t)rowB * TT + u) * 8;
        float4 d4 = __ldg(reinterpret_cast<const float4*>(bp));
        bB[u][0] = d4.x; bB[u][1] = d4.y; bB[u][2] = d4.z; bB[u][3] = d4.w;
        bB[u][4] = __ldg(bp + 4);
    }

#pragma unroll 1
    for (int tb = 0; tb < TT; tb += 4) {
#pragma unroll
        for (int u = 0; u < 4; u++) {
            const int t = tb + u;
            // ---- row A step ----
            float slA0 = fmaf(sA0, aL, bA[u][0]);
            float slA1 = fmaf(sA1, aT, bA[u][1]);
            float slA2 = fmaf(sA2, gc, fmaf(sA3, gs, bA[u][2]));
            float slA3 = fmaf(sA3, gc, fmaf(sA2, ngs, bA[u][3]));
            float slA4 = fmaf(sA4, aR, bA[u][4]);

            float zA0 = fmaf(slA0, w1s[0][0], pA[u].x);
            float zA1 = fmaf(slA0, w1s[0][1], pA[u].y);
            float yA0 = slA1 * w1s[1][0];
            float yA1 = slA1 * w1s[1][1];
            zA0 = fmaf(slA2, w1s[2][0], zA0);
            zA1 = fmaf(slA2, w1s[2][1], zA1);
            yA0 = fmaf(slA3, w1s[3][0], yA0);
            yA1 = fmaf(slA3, w1s[3][1], yA1);
            zA0 = fmaf(slA4, w1s[4][0], zA0);
            zA1 = fmaf(slA4, w1s[4][1], zA1);
            float hA0 = gelu_fast(zA0 + yA0);
            float hA1 = gelu_fast(zA1 + yA1);
            float qA0 = fmaf(hA0, w2v[0][0], hA1 * w2v[1][0]);
            float qA1 = fmaf(hA0, w2v[0][1], hA1 * w2v[1][1]);
            float qA2 = fmaf(hA0, w2v[0][2], hA1 * w2v[1][2]);
            float qA3 = fmaf(hA0, w2v[0][3], hA1 * w2v[1][3]);
            float qA4 = fmaf(hA0, w2v[0][4], hA1 * w2v[1][4]);

            // ---- row B step (independent chain, interleaves with A) ----
            float slB0 = fmaf(sB0, aL, bB[u][0]);
            float slB1 = fmaf(sB1, aT, bB[u][1]);
            float slB2 = fmaf(sB2, gc, fmaf(sB3, gs, bB[u][2]));
            float slB3 = fmaf(sB3, gc, fmaf(sB2, ngs, bB[u][3]));
            float slB4 = fmaf(sB4, aR, bB[u][4]);

            float zB0 = fmaf(slB0, w1s[0][0], pB[u].x);
            float zB1 = fmaf(slB0, w1s[0][1], pB[u].y);
            float yB0 = slB1 * w1s[1][0];
            float yB1 = slB1 * w1s[1][1];
            zB0 = fmaf(slB2, w1s[2][0], zB0);
            zB1 = fmaf(slB2, w1s[2][1], zB1);
            yB0 = fmaf(slB3, w1s[3][0], yB0);
            yB1 = fmaf(slB3, w1s[3][1], yB1);
            zB0 = fmaf(slB4, w1s[4][0], zB0);
            zB1 = fmaf(slB4, w1s[4][1], zB1);
            float hB0 = gelu_fast(zB0 + yB0);
            float hB1 = gelu_fast(zB1 + yB1);
            float qB0 = fmaf(hB0, w2v[0][0], hB1 * w2v[1][0]);
            float qB1 = fmaf(hB0, w2v[0][1], hB1 * w2v[1][1]);
            float qB2 = fmaf(hB0, w2v[0][2], hB1 * w2v[1][2]);
            float qB3 = fmaf(hB0, w2v[0][3], hB1 * w2v[1][3]);
            float qB4 = fmaf(hB0, w2v[0][4], hB1 * w2v[1][4]);

            // ---- prefetch t+4, both rows (pad rows make this safe) ----
            pA[u] = __ldg(reinterpret_cast<const float2*>(
                g_pre + ((size_t)rowA * TT + t + 4) * HH + j0));
            pB[u] = __ldg(reinterpret_cast<const float2*>(
                g_pre + ((size_t)rowB * TT + t + 4) * HH + j0));
            const float* ap = g_ball + ((size_t)rowA * TT + t + 4) * 8;
            float4 c4 = __ldg(reinterpret_cast<const float4*>(ap));
            bA[u][0] = c4.x; bA[u][1] = c4.y; bA[u][2] = c4.z; bA[u][3] = c4.w;
            bA[u][4] = __ldg(ap + 4);
            const float* bp = g_ball + ((size_t)rowB * TT + t + 4) * 8;
            float4 d4 = __ldg(reinterpret_cast<const float4*>(bp));
            bB[u][0] = d4.x; bB[u][1] = d4.y; bB[u][2] = d4.z; bB[u][3] = d4.w;
            bB[u][4] = __ldg(bp + 4);

            // ---- reductions (10 full-warp REDUX) ----
            int iA0 = redux_add_s32(__float2int_rn(qA0));
            int iA1 = redux_add_s32(__float2int_rn(qA1));
            int iA2 = redux_add_s32(__float2int_rn(qA2));
            int iA3 = redux_add_s32(__float2int_rn(qA3));
            int iA4 = redux_add_s32(__float2int_rn(qA4));
            int iB0 = redux_add_s32(__float2int_rn(qB0));
            int iB1 = redux_add_s32(__float2int_rn(qB1));
            int iB2 = redux_add_s32(__float2int_rn(qB2));
            int iB3 = redux_add_s32(__float2int_rn(qB3));
            int iB4 = redux_add_s32(__float2int_rn(qB4));

            sA0 = fmaf(cs, tanh_fast(fmaf(__int2float_rn(iA0), FXSI, bc[0])), slA0);
            sA1 = fmaf(cs, tanh_fast(fmaf(__int2float_rn(iA1), FXSI, bc[1])), slA1);
            sA2 = fmaf(cs, tanh_fast(fmaf(__int2float_rn(iA2), FXSI, bc[2])), slA2);
            sA3 = fmaf(cs, tanh_fast(fmaf(__int2float_rn(iA3), FXSI, bc[3])), slA3);
            sA4 = fmaf(cs, tanh_fast(fmaf(__int2float_rn(iA4), FXSI, bc[4])), slA4);
            sB0 = fmaf(cs, tanh_fast(fmaf(__int2float_rn(iB0), FXSI, bc[0])), slB0);
            sB1 = fmaf(cs, tanh_fast(fmaf(__int2float_rn(iB1), FXSI, bc[1])), slB1);
            sB2 = fmaf(cs, tanh_fast(fmaf(__int2float_rn(iB2), FXSI, bc[2])), slB2);
            sB3 = fmaf(cs, tanh_fast(fmaf(__int2float_rn(iB3), FXSI, bc[3])), slB3);
            sB4 = fmaf(cs, tanh_fast(fmaf(__int2float_rn(iB4), FXSI, bc[4])), slB4);
        }
    }

    if (lane == 0) {
        out[rowA * 5 + 0] = sA0;
        out[rowA * 5 + 1] = sA1;
        out[rowA * 5 + 2] = sA2;
        out[rowA * 5 + 3] = sA3;
        out[rowA * 5 + 4] = sA4;
        out[rowB * 5 + 0] = sB0;
        out[rowB * 5 + 1] = sB1;
        out[rowB * 5 + 2] = sB2;
        out[rowB * 5 + 3] = sB3;
        out[rowB * 5 + 4] = sB4;
    }
}

// =====================================================================
extern "C" void kernel_launch(void* const* d_in, const int* in_sizes, int n_in,
                              void* d_out, int out_size) {
    const float* x = (const float*)d_in[0];
    const float* W1 = (const float*)d_in[1];
    const float* b1 = (const float*)d_in[2];
    const float* ln_g = (const float*)d_in[3];
    const float* ln_b = (const float*)d_in[4];
    const float* W_inn = (const float*)d_in[5];
    const float* b_inn = (const float*)d_in[6];
    const float* Wc1 = (const float*)d_in[7];
    const float* bc1 = (const float*)d_in[8];
    const float* Wc2 = (const float*)d_in[9];
    const float* bc2 = (const float*)d_in[10];
    const float* corr_scale = (const float*)d_in[11];
    const float* raw_aL = (const float*)d_in[12];
    const float* raw_aT = (const float*)d_in[13];
    const float* raw_g = (const float*)d_in[14];
    const float* raw_aR = (const float*)d_in[15];
    const float* omega = (const float*)d_in[16];
    float* out = (float*)d_out;

    cudaFuncSetAttribute(phase1_kernel, cudaFuncAttributeMaxDynamicSharedMemorySize,
                         P1_SMEM_BYTES);

    phase1_kernel<<<(BB * TT) / 128, 256, P1_SMEM_BYTES>>>(
        x, W1, b1, ln_g, ln_b, W_inn, b_inn, Wc1, bc1);
    scan_kernel<<<BB / 2, 32>>>(Wc1, Wc2, bc2, corr_scale, raw_aL, raw_aT, raw_g,
                                raw_aR, omega, out);
}